// round 15
// baseline (speedup 1.0000x reference)
#include <cuda_runtime.h>
#include <cuda_fp16.h>
#include <math.h>
#include <stdint.h>

// ---------------- problem constants ----------------
#define T_STEPS 1024
#define D_IN    2048
#define S_DIM   1024
#define O_DIM   512
#define M_DIM   48
#define G4      4096
#define K_PRE   2560
#define NCTA    128
#define XROWS   1536
#define LN_EPS  1e-5f
#define TPB     512
#define NMEM    96                // memory CTAs

#define ACC_STR 32                // 128B line per accumulator column
#define ACC_COLS 776

#define WSL_HALF2   (768*32)          // 1536 rows paired -> 768 half2 rows x 32 cols
#define WRW_HALF2   (24*512)          // 48 p-rows paired -> 24 x 512 cols
#define WSLICE_F    (8*768)           // per-CTA 8-row projection slice (753 used)
#define DYN_SMEM    ((WSL_HALF2 + WRW_HALF2) * 4 + WSLICE_F * 4)

// ---------------- device globals ----------------
__device__ float g_pre[T_STEPS * G4];          // inputs@W_inp + lab@(W_lab - W_err) + b_lstm
__device__ float g_Wrw[M_DIM * O_DIM];         // (W_rproj @ W_out): [p][j]
__device__ float g_bcomb[O_DIM];               // b_rproj @ W_out + b_out
__device__ float g_h[2][S_DIM];                // parity double-buffered h
__device__ float g_acc[2][ACC_COLS*ACC_STR];   // parity proj accumulators, 128B/column
__device__ float g_ap[96];                     // a partials [48][2]
__device__ float g_bp[96];                     // b partials [48][2]
__device__ float g_ssp[2][96];                 // sumsq partials, parity buffered
__device__ unsigned g_cS12[64];                // counters in distinct lines
__device__ unsigned g_cF[64];

__device__ __forceinline__ float sigf(float x){ return 1.f/(1.f + expf(-x)); }

__device__ __forceinline__ float wsum(float v){
    #pragma unroll
    for (int o = 16; o > 0; o >>= 1) v += __shfl_xor_sync(0xffffffffu, v, o);
    return v;
}

__device__ __forceinline__ unsigned ld_acq(const unsigned* p){
    unsigned v;
    asm volatile("ld.acquire.gpu.u32 %0, [%1];" : "=r"(v) : "l"(p) : "memory");
    return v;
}

// ---------------- dummies (shift ncu -s window onto fw_step) ----------------
__global__ void fw_dummy0(){}
__global__ void fw_dummy1(){}
__global__ void fw_dummy2(){}

// ---------------- setup: Wrw/bcomb + counters + acc zero ----------------
__global__ __launch_bounds__(512) void fw_setup(const float* __restrict__ W_rproj,
                                                const float* __restrict__ b_rproj,
                                                const float* __restrict__ W_out,
                                                const float* __restrict__ b_out){
    const int bb = blockIdx.x;
    const int tid = threadIdx.x;
    if (bb < 49){
        int m = bb;              // 0..48
        int j = tid;             // 0..511
        float acc = 0.f;
        if (m < M_DIM){
            for (int s = 0; s < S_DIM; ++s)
                acc = fmaf(W_rproj[(size_t)m*S_DIM + s], W_out[(size_t)s*512 + j], acc);
            g_Wrw[m*O_DIM + j] = acc;
        } else {
            for (int s = 0; s < S_DIM; ++s)
                acc = fmaf(b_rproj[s], W_out[(size_t)s*512 + j], acc);
            g_bcomb[j] = acc + b_out[j];
        }
    } else {
        if (tid == 0){ g_cS12[0] = 0u; g_cF[0] = 0u; }
        for (int i = tid; i < 2*ACC_COLS*ACC_STR; i += 512) ((float*)g_acc)[i] = 0.f;
    }
}

// ---------------- pre[t][j] = inputs[t]@W_inp + labels[t-1]@(W_lab - W_err) + b_lstm ----------------
__global__ __launch_bounds__(256) void pre_gemm(const float* __restrict__ inputs,
                                                const float* __restrict__ labels,
                                                const float* __restrict__ W_lstm,
                                                const float* __restrict__ b_lstm){
    __shared__ float As[16][132];
    __shared__ float Bs[16][68];
    const int bm = blockIdx.y * 128;
    const int bn = blockIdx.x * 64;
    const int tid = threadIdx.x;
    const int tx = tid & 15, ty = tid >> 4;
    const int atr = tid >> 1, akc = (tid & 1) * 8;
    const int bkr = tid >> 4, bjc = (tid & 15) * 4;

    float acc[8][4];
    #pragma unroll
    for (int u = 0; u < 8; ++u)
        #pragma unroll
        for (int v = 0; v < 4; ++v) acc[u][v] = 0.f;

    for (int k0 = 0; k0 < K_PRE; k0 += 16){
        {
            int t = bm + atr;
            int k = k0 + akc;
            float4 a0, a1;
            if (k0 < D_IN){
                const float* p = &inputs[(size_t)t * D_IN + k];
                a0 = *(const float4*)p; a1 = *(const float4*)(p + 4);
            } else if (t > 0){
                const float* p = &labels[(size_t)(t-1) * O_DIM + (k - D_IN)];
                a0 = *(const float4*)p; a1 = *(const float4*)(p + 4);
            } else {
                a0 = make_float4(0.f,0.f,0.f,0.f); a1 = a0;
            }
            As[akc+0][atr] = a0.x; As[akc+1][atr] = a0.y;
            As[akc+2][atr] = a0.z; As[akc+3][atr] = a0.w;
            As[akc+4][atr] = a1.x; As[akc+5][atr] = a1.y;
            As[akc+6][atr] = a1.z; As[akc+7][atr] = a1.w;
        }
        {
            int krow = k0 + bkr;
            if (krow < D_IN){
                *(float4*)&Bs[bkr][bjc] = *(const float4*)&W_lstm[(size_t)krow * G4 + bn + bjc];
            } else {
                float4 wl = *(const float4*)&W_lstm[(size_t)(krow + 512) * G4 + bn + bjc];
                float4 we = *(const float4*)&W_lstm[(size_t)krow * G4 + bn + bjc];
                float4 d; d.x = wl.x - we.x; d.y = wl.y - we.y; d.z = wl.z - we.z; d.w = wl.w - we.w;
                *(float4*)&Bs[bkr][bjc] = d;
            }
        }
        __syncthreads();
        #pragma unroll
        for (int kk = 0; kk < 16; ++kk){
            float a[8], bb[4];
            *(float4*)&a[0] = *(float4*)&As[kk][ty*8];
            *(float4*)&a[4] = *(float4*)&As[kk][ty*8+4];
            *(float4*)&bb[0] = *(float4*)&Bs[kk][tx*4];
            #pragma unroll
            for (int u = 0; u < 8; ++u)
                #pragma unroll
                for (int v = 0; v < 4; ++v)
                    acc[u][v] = fmaf(a[u], bb[v], acc[u][v]);
        }
        __syncthreads();
    }
    #pragma unroll
    for (int u = 0; u < 8; ++u){
        int t = bm + ty*8 + u;
        int j = bn + tx*4;
        float4 bv = *(const float4*)&b_lstm[j];
        float4 o;
        o.x = acc[u][0] + bv.x; o.y = acc[u][1] + bv.y;
        o.z = acc[u][2] + bv.z; o.w = acc[u][3] + bv.w;
        *(float4*)&g_pre[(size_t)t * G4 + j] = o;
    }
}

// ---------------- persistent stepper ----------------
__global__ __launch_bounds__(TPB, 1) void fw_step(
    const float* __restrict__ W_lstm,
    const float* __restrict__ W_out,
    const float* __restrict__ W_write, const float* __restrict__ W_read,
    const float* __restrict__ b_write, const float* __restrict__ b_read,
    float* __restrict__ dout)
{
    extern __shared__ __align__(16) char dsm[];
    __half2* Wsl    = (__half2*)dsm;                              // [768][32] row-pairs
    __half2* WrwS   = (__half2*)(dsm + WSL_HALF2*4);              // [24][512] p-pairs
    float*   Wslice = (float*)(dsm + (WSL_HALF2 + WRW_HALF2)*4);  // [8][768] proj rows
    __shared__ float xs[XROWS];          // [out(512) | h(1024)]
    __shared__ float mseg[1152];         // this CTA's fast-weight memory segment
    __shared__ float sa[48], sbv[48], sv[48];
    __shared__ float sk1[48], sk2[48], sn[48], se[48];     // prev-step keys
    __shared__ float sk1c[48], sk2c[48], snc[48], sec[48]; // current-step keys
    __shared__ float sdelta[48], snln[48];
    __shared__ float sssp[96];
    __shared__ float pred[16][33];
    __shared__ float sgate[32];
    __shared__ float harr[8];
    __shared__ float c_s[8];
    __shared__ float redf[16];
    __shared__ float red2[16][2];
    __shared__ float sscal[4];           // [0]=upd_beta [1]=upd_inv [2]=beta_raw

    const int tid = threadIdx.x;
    const int b = blockIdx.x;
    const int lane = tid & 31, warp = tid >> 5;
    const bool isMem = (b < NMEM);

    // per-thread memory-segment element indices (fixed per CTA)
    int mai[3], mbi[3];
    #pragma unroll
    for (int s = 0; s < 3; ++s){
        int e2 = tid + s*TPB;
        int jjv = (b & 1)*1152 + e2;
        int ai = jjv / 48;
        mai[s] = ai; mbi[s] = jjv - ai*48;
    }

    // ---- one-time init ----
    for (int idx = tid; idx < WSL_HALF2; idx += TPB){
        int p2 = idx >> 5, c = idx & 31;
        int r0 = p2*2, r1 = p2*2 + 1;
        int g0 = (r0 < 512) ? (2048 + r0) : (2560 + r0);  // err rows (take out), then h rows
        int g1 = (r1 < 512) ? (2048 + r1) : (2560 + r1);
        int j = ((c >> 3) << 10) + b*8 + (c & 7);
        float w0 = W_lstm[(size_t)g0 * G4 + j];
        float w1 = W_lstm[(size_t)g1 * G4 + j];
        Wsl[idx] = __floats2half2_rn(w0, w1);
    }
    for (int idx = tid; idx < WRW_HALF2; idx += TPB){
        int p2 = idx >> 9, j = idx & 511;
        WrwS[idx] = __floats2half2_rn(g_Wrw[(p2*2)*O_DIM + j], g_Wrw[(p2*2+1)*O_DIM + j]);
    }
    #pragma unroll
    for (int k = 0; k < 8; ++k){
        int r = b*8 + k;
        for (int j = tid; j < 768; j += TPB){
            float v = 0.f;
            if      (j < 512) v = W_out[(size_t)r*512 + j];
            else if (j < 657) v = W_write[(size_t)r*145 + (j-512)];
            else if (j < 753) v = W_read[(size_t)r*96 + (j-657)];
            Wslice[k*768 + j] = v;
        }
    }
    for (int i = tid; i < 1152; i += TPB) mseg[i] = 0.f;
    if (tid < 8) c_s[tid] = 0.f;
    if (tid < 48){ sdelta[tid]=0.f; sk1[tid]=0.f; sk2[tid]=0.f; snln[tid]=0.f; }
    if (tid == 0){ sscal[0] = 0.f; sscal[1] = 1.f; }
    unsigned tS = 0, tF = 0;
    float pf_h0 = 0.f, pf_h1 = 0.f;
    __syncthreads();

    for (int t = 0; t < T_STEPS + 1; ++t){
        const float* accP = g_acc[(t-1)&1];   // prev-step accumulator (phaseOut)
        float* accC = g_acc[t&1];             // current-step accumulator

        // ======== phaseOut: finish step t-1 (scalars, out) ========
        if (t > 0){
            if (tid < 48){
                sa[tid]  = __ldcg(&g_ap[tid*2]) + __ldcg(&g_ap[tid*2+1]);
                sbv[tid] = __ldcg(&g_bp[tid*2]) + __ldcg(&g_bp[tid*2+1]);
                sv[tid]  = tanhf(__ldcg(&accP[(608+tid)*ACC_STR]) + __ldg(&b_write[96+tid]));
                sk1[tid] = tanhf(__ldcg(&accP[(512+tid)*ACC_STR]) + __ldg(&b_write[tid]));
                sk2[tid] = tanhf(__ldcg(&accP[(560+tid)*ACC_STR]) + __ldg(&b_write[48+tid]));
                sn[tid]  = tanhf(__ldcg(&accP[(657+tid)*ACC_STR]) + __ldg(&b_read[tid]));
                se[tid]  = tanhf(__ldcg(&accP[(705+tid)*ACC_STR]) + __ldg(&b_read[48+tid]));
            }
            if (tid >= 64 && tid < 160) sssp[tid-64] = __ldcg(&g_ssp[(t-1)&1][tid-64]);
            if (tid == 63) sscal[2] = __ldcg(&accP[656*ACC_STR]) + __ldg(&b_write[144]);
            __syncthreads();
            if (tid < 32){
                const int l = tid; const bool h1 = (l < 16); const int i1 = l + 32;
                float SS  = wsum(sssp[l] + sssp[l+32] + sssp[l+64]);
                float k1n = wsum(sk1[l]*sn[l]  + (h1 ? sk1[i1]*sn[i1] : 0.f));
                float k2e = wsum(sk2[l]*se[l]  + (h1 ? sk2[i1]*se[i1] : 0.f));
                float k1q = wsum(sk1[l]*sk1[l] + (h1 ? sk1[i1]*sk1[i1] : 0.f));
                float k2q = wsum(sk2[l]*sk2[l] + (h1 ? sk2[i1]*sk2[i1] : 0.f));
                float invc = 1.f / fmaxf(1.f, sqrtf(SS));
                float beta = sigf(sscal[2]);
                float d0 = sv[l] - invc*sa[l];
                float d1 = h1 ? (sv[i1] - invc*sa[i1]) : 0.f;
                float da = wsum(d0*sa[l] + (h1 ? d1*sa[i1] : 0.f));
                float dd = wsum(d0*d0 + d1*d1);
                float skr = k1n * k2e;
                float SSP = invc*invc*SS + 2.f*invc*beta*da + beta*beta*dd*k1q*k2q;
                float invn = 1.f / fmaxf(1.f, sqrtf(SSP));
                float nv0 = invn * (invc*sbv[l]  + beta*d0*skr);
                float nv1 = h1 ? invn * (invc*sbv[i1] + beta*d1*skr) : 0.f;
                float mean = wsum(nv0 + nv1) * (1.f/48.f);
                float c0 = nv0 - mean, c1 = nv1 - mean;
                float var = wsum(c0*c0 + (h1 ? c1*c1 : 0.f)) * (1.f/48.f);
                float rs = 1.f / sqrtf(var + LN_EPS);
                snln[l] = c0 * rs;
                if (h1) snln[i1] = c1 * rs;
                sdelta[l] = d0;
                if (h1) sdelta[i1] = d1;
                if (l == 0){ sscal[0] = beta; sscal[1] = invc; }
            }
            __syncthreads();
            // out_{t-1}: one column per thread; Wrw from SMEM (fp16 pairs)
            {
                const int j = tid;
                float o = __ldcg(&accP[j*ACC_STR]) + g_bcomb[j];
                #pragma unroll
                for (int p2 = 0; p2 < 24; ++p2){
                    float2 w = __half22float2(WrwS[p2*512 + j]);
                    o = fmaf(snln[p2*2], w.x, fmaf(snln[p2*2+1], w.y, o));
                }
                o = tanhf(o * 0.1f) * 10.f;
                if (b == 0) dout[(size_t)(t-1)*O_DIM + j] = o;
                xs[j] = o;
            }
            xs[512  + tid] = pf_h0;
            xs[1024 + tid] = pf_h1;
        } else {
            for (int i = tid; i < XROWS; i += TPB) xs[i] = 0.f;
        }
        if (t == T_STEPS) break;
        __syncthreads();

        // ======== phase 1: gates + cell + mseg update + partial projections ========
        {
            float gp = 0.f;
            if (tid < 32){
                int j = ((tid >> 3) << 10) + b*8 + (tid & 7);
                gp = __ldg(&g_pre[(size_t)t * G4 + j]);
            }
            const int c = lane, rc = warp;
            const int r0 = rc * 96;          // xs row base
            const int pr0 = rc * 48;         // pair base
            float acc = 0.f;
            #pragma unroll
            for (int pp = 0; pp < 48; pp += 2){
                float4 xv = *(float4*)&xs[r0 + pp*2];
                float2 w0 = __half22float2(Wsl[(pr0+pp  )*32 + c]);
                float2 w1 = __half22float2(Wsl[(pr0+pp+1)*32 + c]);
                acc = fmaf(xv.x, w0.x, acc);
                acc = fmaf(xv.y, w0.y, acc);
                acc = fmaf(xv.z, w1.x, acc);
                acc = fmaf(xv.w, w1.y, acc);
            }
            pred[rc][c] = acc;

            // fast-weight physical update (prev-step params) + sum-of-squares
            if (isMem){
                const int p = b >> 1;
                const float coef = sscal[0] * sdelta[p];
                const float uinv = sscal[1];
                float fss = 0.f;
                #pragma unroll
                for (int s = 0; s < 3; ++s){
                    int e2 = tid + s*TPB;
                    if (e2 < 1152){
                        float m = fmaf(coef, sk1[mai[s]]*sk2[mbi[s]], uinv * mseg[e2]);
                        mseg[e2] = m;
                        fss = fmaf(m, m, fss);
                    }
                }
                fss = wsum(fss);
                if (lane == 0) redf[warp] = fss;
            }
            __syncthreads();
            if (tid < 32){
                float g = 0.f;
                #pragma unroll
                for (int r2 = 0; r2 < 16; ++r2) g += pred[r2][tid];
                sgate[tid] = g + gp;
            }
            if (tid == 32 && isMem){
                float s = 0.f;
                #pragma unroll
                for (int w = 0; w < 16; ++w) s += redf[w];
                __stcg(&g_ssp[t&1][b], s);
            }
            __syncthreads();
            if (tid < 8){
                float iv = sgate[tid], gv = sgate[8+tid], fv = sgate[16+tid], ov = sgate[24+tid];
                float cn = sigf(fv + 1.f) * c_s[tid] + sigf(iv) * tanhf(gv);
                c_s[tid] = cn;
                float hv = sigf(ov) * tanhf(cn);
                harr[tid] = hv;
                __stcg(&g_h[t&1][b*8 + tid], hv);
            }
            __syncthreads();
            // partial projections: this CTA's 8 h-rows into all 753 columns (padded atomics)
            {
                float vA = 0.f;
                #pragma unroll
                for (int k = 0; k < 8; ++k)
                    vA = fmaf(harr[k], Wslice[k*768 + tid], vA);
                atomicAdd(&accC[tid*ACC_STR], vA);
                if (tid < 241){
                    float vB = 0.f;
                    #pragma unroll
                    for (int k = 0; k < 8; ++k)
                        vB = fmaf(harr[k], Wslice[k*768 + 512 + tid], vB);
                    atomicAdd(&accC[(512 + tid)*ACC_STR], vB);
                }
            }
        }
        // ---- S12: full barrier ----
        __syncthreads();
        if (tid == 0){ __threadfence(); atomicAdd(&g_cS12[0], 1u); }
        tS += NCTA;
        if (tid == 0){ while (ld_acq(&g_cS12[0]) < tS) {} }
        __syncthreads();

        // ======== phase 3: memory dots (mem CTAs) + next-parity zeroing (all) ========
        if (isMem){
            if (tid < 48){
                sk1c[tid] = tanhf(__ldcg(&accC[(512+tid)*ACC_STR]) + __ldg(&b_write[tid]));
                sk2c[tid] = tanhf(__ldcg(&accC[(560+tid)*ACC_STR]) + __ldg(&b_write[48+tid]));
                snc[tid]  = tanhf(__ldcg(&accC[(657+tid)*ACC_STR]) + __ldg(&b_read[tid]));
                sec[tid]  = tanhf(__ldcg(&accC[(705+tid)*ACC_STR]) + __ldg(&b_read[48+tid]));
            }
            __syncthreads();
            float fa = 0.f, fb = 0.f;
            #pragma unroll
            for (int s = 0; s < 3; ++s){
                int e2 = tid + s*TPB;
                if (e2 < 1152){
                    float m = mseg[e2];
                    fa = fmaf(m, sk1c[mai[s]]*sk2c[mbi[s]], fa);
                    fb = fmaf(m, snc[mai[s]]*sec[mbi[s]], fb);
                }
            }
            #pragma unroll
            for (int o = 16; o > 0; o >>= 1){
                fa += __shfl_xor_sync(0xffffffffu, fa, o);
                fb += __shfl_xor_sync(0xffffffffu, fb, o);
            }
            if (lane == 0){ red2[warp][0] = fa; red2[warp][1] = fb; }
            __syncthreads();
            if (tid == 0){
                float A = 0.f, B = 0.f;
                #pragma unroll
                for (int w = 0; w < 16; ++w){ A += red2[w][0]; B += red2[w][1]; }
                __stcg(&g_ap[b], A);
                __stcg(&g_bp[b], B);
            }
        }
        // zero own columns of the NEXT-parity accumulator (safe: after S12(t), all readers done)
        if (tid < 6){
            int co = b*6 + tid;
            if (co < 753) __stcg(&g_acc[(t+1)&1][co*ACC_STR], 0.f);
        }
        // prefetch h for phaseOut xs
        pf_h0 = __ldcg(&g_h[t&1][tid]);
        pf_h1 = __ldcg(&g_h[t&1][512 + tid]);
        // ---- F: full barrier ----
        __syncthreads();
        if (tid == 0){ __threadfence(); atomicAdd(&g_cF[0], 1u); }
        tF += NCTA;
        if (tid == 0){ while (ld_acq(&g_cF[0]) < tF) {} }
        __syncthreads();
    }
}

// ---------------- launch ----------------
extern "C" void kernel_launch(void* const* d_in, const int* in_sizes, int n_in,
                              void* d_out, int out_size) {
    const float* inputs  = (const float*)d_in[0];
    const float* labels  = (const float*)d_in[1];
    const float* W_lstm  = (const float*)d_in[2];
    const float* b_lstm  = (const float*)d_in[3];
    const float* W_write = (const float*)d_in[4];
    const float* b_write = (const float*)d_in[5];
    const float* W_read  = (const float*)d_in[6];
    const float* b_read  = (const float*)d_in[7];
    const float* W_rproj = (const float*)d_in[8];
    const float* b_rproj = (const float*)d_in[9];
    const float* W_out   = (const float*)d_in[10];
    const float* b_out   = (const float*)d_in[11];
    float* out = (float*)d_out;

    cudaFuncSetAttribute(fw_step, cudaFuncAttributeMaxDynamicSharedMemorySize, DYN_SMEM);

    fw_dummy0<<<1, 32>>>();
    fw_dummy1<<<1, 32>>>();
    fw_dummy2<<<1, 32>>>();
    fw_setup<<<50, 512>>>(W_rproj, b_rproj, W_out, b_out);
    pre_gemm<<<dim3(64, 8), 256>>>(inputs, labels, W_lstm, b_lstm);
    fw_step<<<NCTA, TPB, DYN_SMEM>>>(W_lstm, W_out, W_write, W_read, b_write, b_read, out);
}

// round 16
// speedup vs baseline: 1.1735x; 1.1735x over previous
#include <cuda_runtime.h>
#include <cuda_fp16.h>
#include <math.h>
#include <stdint.h>

// ---------------- problem constants ----------------
#define T_STEPS 1024
#define D_IN    2048
#define S_DIM   1024
#define O_DIM   512
#define M_DIM   48
#define G4      4096
#define K_PRE   2560
#define NCTA    128
#define XROWS   1536
#define LN_EPS  1e-5f
#define TPB     512
#define NMEM    96                // memory CTAs

#define WSL_HALF2   (768*32)          // 1536 rows paired -> 768 half2 rows x 32 cols
#define WRW_HALF2   (24*512)          // 48 p-rows paired -> 24 x 512 cols
#define WSLICE_F    (8*768)           // per-CTA 8-row projection slice (753 used)
#define DYN_SMEM    ((WSL_HALF2 + WRW_HALF2) * 4 + WSLICE_F * 4)

// ---------------- device globals ----------------
__device__ float g_pre[T_STEPS * G4];          // inputs@W_inp + lab@(W_lab - W_err) + b_lstm
__device__ float g_Wrw[M_DIM * O_DIM];         // (W_rproj @ W_out): [p][j]
__device__ float g_bcomb[O_DIM];               // b_rproj @ W_out + b_out
__device__ float g_h[2][S_DIM];                // parity double-buffered h
__device__ float g_acc[2][1024];               // parity proj accumulators [uh(512)|wr(145)|rd(96)]
__device__ float g_ap[96];                     // a partials [48][2]
__device__ float g_bp[96];                     // b partials [48][2]
__device__ float g_ssp[2][96];                 // sumsq partials, parity buffered
__device__ unsigned g_cS12[64];                // counters in distinct lines
__device__ unsigned g_cF[64];

__device__ __forceinline__ float sigf(float x){ return 1.f/(1.f + expf(-x)); }

__device__ __forceinline__ float wsum(float v){
    #pragma unroll
    for (int o = 16; o > 0; o >>= 1) v += __shfl_xor_sync(0xffffffffu, v, o);
    return v;
}

__device__ __forceinline__ unsigned ld_acq(const unsigned* p){
    unsigned v;
    asm volatile("ld.acquire.gpu.u32 %0, [%1];" : "=r"(v) : "l"(p) : "memory");
    return v;
}

__device__ __forceinline__ void red_release(unsigned* p){
    asm volatile("red.release.gpu.global.add.u32 [%0], %1;" :: "l"(p), "r"(1u) : "memory");
}

// ---------------- dummies (shift ncu -s window onto fw_step) ----------------
__global__ void fw_dummy0(){}
__global__ void fw_dummy1(){}
__global__ void fw_dummy2(){}

// ---------------- setup: Wrw/bcomb + counters + acc zero ----------------
__global__ __launch_bounds__(512) void fw_setup(const float* __restrict__ W_rproj,
                                                const float* __restrict__ b_rproj,
                                                const float* __restrict__ W_out,
                                                const float* __restrict__ b_out){
    const int bb = blockIdx.x;
    const int tid = threadIdx.x;
    if (bb < 49){
        int m = bb;              // 0..48
        int j = tid;             // 0..511
        float acc = 0.f;
        if (m < M_DIM){
            for (int s = 0; s < S_DIM; ++s)
                acc = fmaf(W_rproj[(size_t)m*S_DIM + s], W_out[(size_t)s*512 + j], acc);
            g_Wrw[m*O_DIM + j] = acc;
        } else {
            for (int s = 0; s < S_DIM; ++s)
                acc = fmaf(b_rproj[s], W_out[(size_t)s*512 + j], acc);
            g_bcomb[j] = acc + b_out[j];
        }
    } else {
        if (tid == 0){ g_cS12[0] = 0u; g_cF[0] = 0u; }
        for (int i = tid; i < 2048; i += 512) ((float*)g_acc)[i] = 0.f;
    }
}

// ---------------- pre[t][j] = inputs[t]@W_inp + labels[t-1]@(W_lab - W_err) + b_lstm ----------------
__global__ __launch_bounds__(256) void pre_gemm(const float* __restrict__ inputs,
                                                const float* __restrict__ labels,
                                                const float* __restrict__ W_lstm,
                                                const float* __restrict__ b_lstm){
    __shared__ float As[16][132];
    __shared__ float Bs[16][68];
    const int bm = blockIdx.y * 128;
    const int bn = blockIdx.x * 64;
    const int tid = threadIdx.x;
    const int tx = tid & 15, ty = tid >> 4;
    const int atr = tid >> 1, akc = (tid & 1) * 8;
    const int bkr = tid >> 4, bjc = (tid & 15) * 4;

    float acc[8][4];
    #pragma unroll
    for (int u = 0; u < 8; ++u)
        #pragma unroll
        for (int v = 0; v < 4; ++v) acc[u][v] = 0.f;

    for (int k0 = 0; k0 < K_PRE; k0 += 16){
        {
            int t = bm + atr;
            int k = k0 + akc;
            float4 a0, a1;
            if (k0 < D_IN){
                const float* p = &inputs[(size_t)t * D_IN + k];
                a0 = *(const float4*)p; a1 = *(const float4*)(p + 4);
            } else if (t > 0){
                const float* p = &labels[(size_t)(t-1) * O_DIM + (k - D_IN)];
                a0 = *(const float4*)p; a1 = *(const float4*)(p + 4);
            } else {
                a0 = make_float4(0.f,0.f,0.f,0.f); a1 = a0;
            }
            As[akc+0][atr] = a0.x; As[akc+1][atr] = a0.y;
            As[akc+2][atr] = a0.z; As[akc+3][atr] = a0.w;
            As[akc+4][atr] = a1.x; As[akc+5][atr] = a1.y;
            As[akc+6][atr] = a1.z; As[akc+7][atr] = a1.w;
        }
        {
            int krow = k0 + bkr;
            if (krow < D_IN){
                *(float4*)&Bs[bkr][bjc] = *(const float4*)&W_lstm[(size_t)krow * G4 + bn + bjc];
            } else {
                float4 wl = *(const float4*)&W_lstm[(size_t)(krow + 512) * G4 + bn + bjc];
                float4 we = *(const float4*)&W_lstm[(size_t)krow * G4 + bn + bjc];
                float4 d; d.x = wl.x - we.x; d.y = wl.y - we.y; d.z = wl.z - we.z; d.w = wl.w - we.w;
                *(float4*)&Bs[bkr][bjc] = d;
            }
        }
        __syncthreads();
        #pragma unroll
        for (int kk = 0; kk < 16; ++kk){
            float a[8], bb[4];
            *(float4*)&a[0] = *(float4*)&As[kk][ty*8];
            *(float4*)&a[4] = *(float4*)&As[kk][ty*8+4];
            *(float4*)&bb[0] = *(float4*)&Bs[kk][tx*4];
            #pragma unroll
            for (int u = 0; u < 8; ++u)
                #pragma unroll
                for (int v = 0; v < 4; ++v)
                    acc[u][v] = fmaf(a[u], bb[v], acc[u][v]);
        }
        __syncthreads();
    }
    #pragma unroll
    for (int u = 0; u < 8; ++u){
        int t = bm + ty*8 + u;
        int j = bn + tx*4;
        float4 bv = *(const float4*)&b_lstm[j];
        float4 o;
        o.x = acc[u][0] + bv.x; o.y = acc[u][1] + bv.y;
        o.z = acc[u][2] + bv.z; o.w = acc[u][3] + bv.w;
        *(float4*)&g_pre[(size_t)t * G4 + j] = o;
    }
}

// ---------------- persistent stepper ----------------
__global__ __launch_bounds__(TPB, 1) void fw_step(
    const float* __restrict__ W_lstm,
    const float* __restrict__ W_out,
    const float* __restrict__ W_write, const float* __restrict__ W_read,
    const float* __restrict__ b_write, const float* __restrict__ b_read,
    float* __restrict__ dout)
{
    extern __shared__ __align__(16) char dsm[];
    __half2* Wsl    = (__half2*)dsm;                              // [768][32] row-pairs
    __half2* WrwS   = (__half2*)(dsm + WSL_HALF2*4);              // [24][512] p-pairs
    float*   Wslice = (float*)(dsm + (WSL_HALF2 + WRW_HALF2)*4);  // [8][768] proj rows
    __shared__ float xs[XROWS];          // [out(512) | h(1024)]
    __shared__ float mseg[1152];         // this CTA's fast-weight memory segment
    __shared__ float sa[48], sbv[48], sv[48];
    __shared__ float sk1[48], sk2[48], sn[48], se[48];     // prev-step keys
    __shared__ float sk1c[48], sk2c[48], snc[48], sec[48]; // current-step keys
    __shared__ float sdelta[48], snln[48];
    __shared__ float sssp[96];
    __shared__ float pred[16][33];
    __shared__ float sgate[32];
    __shared__ float harr[8];
    __shared__ float c_s[8];
    __shared__ float redf[16];
    __shared__ float red2[16][2];
    __shared__ float sscal[4];           // [0]=upd_beta [1]=upd_inv [2]=beta_raw

    const int tid = threadIdx.x;
    const int b = blockIdx.x;
    const int lane = tid & 31, warp = tid >> 5;
    const bool isMem = (b < NMEM);

    // per-thread memory-segment element indices (fixed per CTA)
    int mai[3], mbi[3];
    #pragma unroll
    for (int s = 0; s < 3; ++s){
        int e2 = tid + s*TPB;
        int jjv = (b & 1)*1152 + e2;
        int ai = jjv / 48;
        mai[s] = ai; mbi[s] = jjv - ai*48;
    }

    // ---- one-time init ----
    for (int idx = tid; idx < WSL_HALF2; idx += TPB){
        int p2 = idx >> 5, c = idx & 31;
        int r0 = p2*2, r1 = p2*2 + 1;
        int g0 = (r0 < 512) ? (2048 + r0) : (2560 + r0);  // err rows (take out), then h rows
        int g1 = (r1 < 512) ? (2048 + r1) : (2560 + r1);
        int j = ((c >> 3) << 10) + b*8 + (c & 7);
        float w0 = W_lstm[(size_t)g0 * G4 + j];
        float w1 = W_lstm[(size_t)g1 * G4 + j];
        Wsl[idx] = __floats2half2_rn(w0, w1);
    }
    for (int idx = tid; idx < WRW_HALF2; idx += TPB){
        int p2 = idx >> 9, j = idx & 511;
        WrwS[idx] = __floats2half2_rn(g_Wrw[(p2*2)*O_DIM + j], g_Wrw[(p2*2+1)*O_DIM + j]);
    }
    #pragma unroll
    for (int k = 0; k < 8; ++k){
        int r = b*8 + k;
        for (int j = tid; j < 768; j += TPB){
            float v = 0.f;
            if      (j < 512) v = W_out[(size_t)r*512 + j];
            else if (j < 657) v = W_write[(size_t)r*145 + (j-512)];
            else if (j < 753) v = W_read[(size_t)r*96 + (j-657)];
            Wslice[k*768 + j] = v;
        }
    }
    for (int i = tid; i < 1152; i += TPB) mseg[i] = 0.f;
    if (tid < 8) c_s[tid] = 0.f;
    if (tid < 48){ sdelta[tid]=0.f; sk1[tid]=0.f; sk2[tid]=0.f; snln[tid]=0.f; }
    if (tid == 0){ sscal[0] = 0.f; sscal[1] = 1.f; }
    unsigned tS = 0, tF = 0;
    float pf_h0 = 0.f, pf_h1 = 0.f, pf_uh = 0.f;
    float pf_v = 0.f, pf_k1 = 0.f, pf_k2 = 0.f, pf_n = 0.f, pf_e = 0.f;
    float pf_ssp = 0.f, pf_beta = 0.f;
    __syncthreads();

    for (int t = 0; t < T_STEPS + 1; ++t){
        float* accC = g_acc[t&1];             // current-step accumulator

        // ======== phaseOut: finish step t-1 (scalars, out) — uses window prefetches ========
        if (t > 0){
            if (tid < 48){
                sa[tid]  = __ldcg(&g_ap[tid*2]) + __ldcg(&g_ap[tid*2+1]);
                sbv[tid] = __ldcg(&g_bp[tid*2]) + __ldcg(&g_bp[tid*2+1]);
                sv[tid]  = tanhf(pf_v);
                sk1[tid] = tanhf(pf_k1);
                sk2[tid] = tanhf(pf_k2);
                sn[tid]  = tanhf(pf_n);
                se[tid]  = tanhf(pf_e);
            }
            if (tid >= 64 && tid < 160) sssp[tid-64] = pf_ssp;
            if (tid == 63) sscal[2] = pf_beta;
            __syncthreads();
            if (tid < 32){
                const int l = tid; const bool h1 = (l < 16); const int i1 = l + 32;
                float SS  = wsum(sssp[l] + sssp[l+32] + sssp[l+64]);
                float k1n = wsum(sk1[l]*sn[l]  + (h1 ? sk1[i1]*sn[i1] : 0.f));
                float k2e = wsum(sk2[l]*se[l]  + (h1 ? sk2[i1]*se[i1] : 0.f));
                float k1q = wsum(sk1[l]*sk1[l] + (h1 ? sk1[i1]*sk1[i1] : 0.f));
                float k2q = wsum(sk2[l]*sk2[l] + (h1 ? sk2[i1]*sk2[i1] : 0.f));
                float invc = 1.f / fmaxf(1.f, sqrtf(SS));
                float beta = sigf(sscal[2]);
                float d0 = sv[l] - invc*sa[l];
                float d1 = h1 ? (sv[i1] - invc*sa[i1]) : 0.f;
                float da = wsum(d0*sa[l] + (h1 ? d1*sa[i1] : 0.f));
                float dd = wsum(d0*d0 + d1*d1);
                float skr = k1n * k2e;
                float SSP = invc*invc*SS + 2.f*invc*beta*da + beta*beta*dd*k1q*k2q;
                float invn = 1.f / fmaxf(1.f, sqrtf(SSP));
                float nv0 = invn * (invc*sbv[l]  + beta*d0*skr);
                float nv1 = h1 ? invn * (invc*sbv[i1] + beta*d1*skr) : 0.f;
                float mean = wsum(nv0 + nv1) * (1.f/48.f);
                float c0 = nv0 - mean, c1 = nv1 - mean;
                float var = wsum(c0*c0 + (h1 ? c1*c1 : 0.f)) * (1.f/48.f);
                float rs = 1.f / sqrtf(var + LN_EPS);
                snln[l] = c0 * rs;
                if (h1) snln[i1] = c1 * rs;
                sdelta[l] = d0;
                if (h1) sdelta[i1] = d1;
                if (l == 0){ sscal[0] = beta; sscal[1] = invc; }
            }
            __syncthreads();
            // out_{t-1}: one column per thread; Wrw from SMEM (fp16 pairs)
            {
                const int j = tid;
                float o = pf_uh + g_bcomb[j];
                #pragma unroll
                for (int p2 = 0; p2 < 24; ++p2){
                    float2 w = __half22float2(WrwS[p2*512 + j]);
                    o = fmaf(snln[p2*2], w.x, fmaf(snln[p2*2+1], w.y, o));
                }
                o = tanhf(o * 0.1f) * 10.f;
                if (b == 0) dout[(size_t)(t-1)*O_DIM + j] = o;
                xs[j] = o;
            }
            xs[512  + tid] = pf_h0;
            xs[1024 + tid] = pf_h1;
        } else {
            for (int i = tid; i < XROWS; i += TPB) xs[i] = 0.f;
        }
        if (t == T_STEPS) break;
        __syncthreads();

        // ======== phase 1: gates + cell + mseg update + partial projections ========
        {
            float gp = 0.f;
            if (tid < 32){
                int j = ((tid >> 3) << 10) + b*8 + (tid & 7);
                gp = __ldg(&g_pre[(size_t)t * G4 + j]);
            }
            const int c = lane, rc = warp;
            const int r0 = rc * 96;          // xs row base
            const int pr0 = rc * 48;         // pair base
            float acc = 0.f;
            #pragma unroll
            for (int pp = 0; pp < 48; pp += 2){
                float4 xv = *(float4*)&xs[r0 + pp*2];
                float2 w0 = __half22float2(Wsl[(pr0+pp  )*32 + c]);
                float2 w1 = __half22float2(Wsl[(pr0+pp+1)*32 + c]);
                acc = fmaf(xv.x, w0.x, acc);
                acc = fmaf(xv.y, w0.y, acc);
                acc = fmaf(xv.z, w1.x, acc);
                acc = fmaf(xv.w, w1.y, acc);
            }
            pred[rc][c] = acc;

            // fast-weight physical update (prev-step params) + sum-of-squares
            if (isMem){
                const int p = b >> 1;
                const float coef = sscal[0] * sdelta[p];
                const float uinv = sscal[1];
                float fss = 0.f;
                #pragma unroll
                for (int s = 0; s < 3; ++s){
                    int e2 = tid + s*TPB;
                    if (e2 < 1152){
                        float m = fmaf(coef, sk1[mai[s]]*sk2[mbi[s]], uinv * mseg[e2]);
                        mseg[e2] = m;
                        fss = fmaf(m, m, fss);
                    }
                }
                fss = wsum(fss);
                if (lane == 0) redf[warp] = fss;
            }
            __syncthreads();
            if (tid < 32){
                float g = 0.f;
                #pragma unroll
                for (int r2 = 0; r2 < 16; ++r2) g += pred[r2][tid];
                sgate[tid] = g + gp;
            }
            if (tid == 32 && isMem){
                float s = 0.f;
                #pragma unroll
                for (int w = 0; w < 16; ++w) s += redf[w];
                __stcg(&g_ssp[t&1][b], s);
            }
            __syncthreads();
            if (tid < 8){
                float iv = sgate[tid], gv = sgate[8+tid], fv = sgate[16+tid], ov = sgate[24+tid];
                float cn = sigf(fv + 1.f) * c_s[tid] + sigf(iv) * tanhf(gv);
                c_s[tid] = cn;
                float hv = sigf(ov) * tanhf(cn);
                harr[tid] = hv;
                __stcg(&g_h[t&1][b*8 + tid], hv);
            }
            __syncthreads();
            // partial projections: this CTA's 8 h-rows into all 753 columns (dense atomics)
            {
                float vA = 0.f;
                #pragma unroll
                for (int k = 0; k < 8; ++k)
                    vA = fmaf(harr[k], Wslice[k*768 + tid], vA);
                atomicAdd(&accC[tid], vA);
                if (tid < 241){
                    float vB = 0.f;
                    #pragma unroll
                    for (int k = 0; k < 8; ++k)
                        vB = fmaf(harr[k], Wslice[k*768 + 512 + tid], vB);
                    atomicAdd(&accC[512 + tid], vB);
                }
            }
        }
        // ---- S12: full barrier (release arrival) ----
        __syncthreads();
        if (tid == 0) red_release(&g_cS12[0]);
        tS += NCTA;
        if (tid == 0){ while (ld_acq(&g_cS12[0]) < tS) {} }
        __syncthreads();

        // ======== phase 3: memory dots (mem CTAs) + next-parity zeroing (all) ========
        if (isMem){
            if (tid < 48){
                sk1c[tid] = tanhf(__ldcg(&accC[512+tid]) + __ldg(&b_write[tid]));
                sk2c[tid] = tanhf(__ldcg(&accC[560+tid]) + __ldg(&b_write[48+tid]));
                snc[tid]  = tanhf(__ldcg(&accC[657+tid]) + __ldg(&b_read[tid]));
                sec[tid]  = tanhf(__ldcg(&accC[705+tid]) + __ldg(&b_read[48+tid]));
            }
            __syncthreads();
            float fa = 0.f, fb = 0.f;
            #pragma unroll
            for (int s = 0; s < 3; ++s){
                int e2 = tid + s*TPB;
                if (e2 < 1152){
                    float m = mseg[e2];
                    fa = fmaf(m, sk1c[mai[s]]*sk2c[mbi[s]], fa);
                    fb = fmaf(m, snc[mai[s]]*sec[mbi[s]], fb);
                }
            }
            #pragma unroll
            for (int o = 16; o > 0; o >>= 1){
                fa += __shfl_xor_sync(0xffffffffu, fa, o);
                fb += __shfl_xor_sync(0xffffffffu, fb, o);
            }
            if (lane == 0){ red2[warp][0] = fa; red2[warp][1] = fb; }
            __syncthreads();
            if (tid == 0){
                float A = 0.f, B = 0.f;
                #pragma unroll
                for (int w = 0; w < 16; ++w){ A += red2[w][0]; B += red2[w][1]; }
                __stcg(&g_ap[b], A);
                __stcg(&g_bp[b], B);
            }
        }
        // zero own columns of the NEXT-parity accumulator (safe: after S12(t), all readers done)
        if (tid < 6){
            int co = b*6 + tid;
            if (co < 753) __stcg(&g_acc[(t+1)&1][co], 0.f);
        }
        // ---- window prefetches for phaseOut(t+1): accC/ssp are final after S12(t) ----
        pf_h0 = __ldcg(&g_h[t&1][tid]);
        pf_h1 = __ldcg(&g_h[t&1][512 + tid]);
        pf_uh = __ldcg(&accC[tid]);
        if (tid < 48){
            pf_v  = __ldcg(&accC[608+tid]) + __ldg(&b_write[96+tid]);
            pf_k1 = __ldcg(&accC[512+tid]) + __ldg(&b_write[tid]);
            pf_k2 = __ldcg(&accC[560+tid]) + __ldg(&b_write[48+tid]);
            pf_n  = __ldcg(&accC[657+tid]) + __ldg(&b_read[tid]);
            pf_e  = __ldcg(&accC[705+tid]) + __ldg(&b_read[48+tid]);
        }
        if (tid >= 64 && tid < 160) pf_ssp = __ldcg(&g_ssp[t&1][tid-64]);
        if (tid == 63) pf_beta = __ldcg(&accC[656]) + __ldg(&b_write[144]);
        // ---- F: full barrier (release arrival) ----
        __syncthreads();
        if (tid == 0) red_release(&g_cF[0]);
        tF += NCTA;
        if (tid == 0){ while (ld_acq(&g_cF[0]) < tF) {} }
        __syncthreads();
    }
}

// ---------------- launch ----------------
extern "C" void kernel_launch(void* const* d_in, const int* in_sizes, int n_in,
                              void* d_out, int out_size) {
    const float* inputs  = (const float*)d_in[0];
    const float* labels  = (const float*)d_in[1];
    const float* W_lstm  = (const float*)d_in[2];
    const float* b_lstm  = (const float*)d_in[3];
    const float* W_write = (const float*)d_in[4];
    const float* b_write = (const float*)d_in[5];
    const float* W_read  = (const float*)d_in[6];
    const float* b_read  = (const float*)d_in[7];
    const float* W_rproj = (const float*)d_in[8];
    const float* b_rproj = (const float*)d_in[9];
    const float* W_out   = (const float*)d_in[10];
    const float* b_out   = (const float*)d_in[11];
    float* out = (float*)d_out;

    cudaFuncSetAttribute(fw_step, cudaFuncAttributeMaxDynamicSharedMemorySize, DYN_SMEM);

    fw_dummy0<<<1, 32>>>();
    fw_dummy1<<<1, 32>>>();
    fw_dummy2<<<1, 32>>>();
    fw_setup<<<50, 512>>>(W_rproj, b_rproj, W_out, b_out);
    pre_gemm<<<dim3(64, 8), 256>>>(inputs, labels, W_lstm, b_lstm);
    fw_step<<<NCTA, TPB, DYN_SMEM>>>(W_lstm, W_out, W_write, W_read, b_write, b_read, out);
}

// round 17
// speedup vs baseline: 1.1895x; 1.0136x over previous
#include <cuda_runtime.h>
#include <cuda_fp16.h>
#include <math.h>
#include <stdint.h>

// ---------------- problem constants ----------------
#define T_STEPS 1024
#define D_IN    2048
#define S_DIM   1024
#define O_DIM   512
#define M_DIM   48
#define G4      4096
#define K_PRE   2560
#define NCTA    128
#define XROWS   1536
#define LN_EPS  1e-5f
#define TPB     512
#define NMEM    48                // memory CTAs: one full row each
#define MROW    2304              // M*M elements per row

#define WSL_HALF2   (768*32)          // 1536 rows paired -> 768 half2 rows x 32 cols
#define WRW_HALF2   (24*512)          // 48 p-rows paired -> 24 x 512 cols
#define WSLICE_F    (8*768)           // per-CTA 8-row projection slice (753 used)
#define DYN_SMEM    ((WSL_HALF2 + WRW_HALF2) * 4 + WSLICE_F * 4)

// ---------------- device globals ----------------
__device__ float g_pre[T_STEPS * G4];          // inputs@W_inp + lab@(W_lab - W_err) + b_lstm
__device__ float g_Wrw[M_DIM * O_DIM];         // (W_rproj @ W_out): [p][j]
__device__ float g_bcomb[O_DIM];               // b_rproj @ W_out + b_out
__device__ float g_h[2][S_DIM];                // parity double-buffered h
__device__ float g_acc[2][1024];               // parity proj accumulators [uh(512)|wr(145)|rd(96)]
__device__ float g_ap[64];                     // a per row (48 used)
__device__ float g_bp[64];                     // b per row (48 used)
__device__ float g_ssp[2][64];                 // sumsq per row, parity buffered
__device__ unsigned g_cS12[64];                // counters in distinct lines
__device__ unsigned g_cF[64];

__device__ __forceinline__ float sigf(float x){ return 1.f/(1.f + expf(-x)); }

__device__ __forceinline__ float wsum(float v){
    #pragma unroll
    for (int o = 16; o > 0; o >>= 1) v += __shfl_xor_sync(0xffffffffu, v, o);
    return v;
}

__device__ __forceinline__ unsigned ld_acq(const unsigned* p){
    unsigned v;
    asm volatile("ld.acquire.gpu.u32 %0, [%1];" : "=r"(v) : "l"(p) : "memory");
    return v;
}

__device__ __forceinline__ void red_release(unsigned* p){
    asm volatile("red.release.gpu.global.add.u32 [%0], %1;" :: "l"(p), "r"(1u) : "memory");
}

// ---------------- dummies (shift ncu -s window onto fw_step) ----------------
__global__ void fw_dummy0(){}
__global__ void fw_dummy1(){}
__global__ void fw_dummy2(){}
__global__ void fw_dummy3(){}
__global__ void fw_dummy4(){}

// ---------------- setup: Wrw/bcomb + counters + acc zero ----------------
__global__ __launch_bounds__(512) void fw_setup(const float* __restrict__ W_rproj,
                                                const float* __restrict__ b_rproj,
                                                const float* __restrict__ W_out,
                                                const float* __restrict__ b_out){
    const int bb = blockIdx.x;
    const int tid = threadIdx.x;
    if (bb < 49){
        int m = bb;              // 0..48
        int j = tid;             // 0..511
        float acc = 0.f;
        if (m < M_DIM){
            for (int s = 0; s < S_DIM; ++s)
                acc = fmaf(W_rproj[(size_t)m*S_DIM + s], W_out[(size_t)s*512 + j], acc);
            g_Wrw[m*O_DIM + j] = acc;
        } else {
            for (int s = 0; s < S_DIM; ++s)
                acc = fmaf(b_rproj[s], W_out[(size_t)s*512 + j], acc);
            g_bcomb[j] = acc + b_out[j];
        }
    } else {
        if (tid == 0){ g_cS12[0] = 0u; g_cF[0] = 0u; }
        for (int i = tid; i < 2048; i += 512) ((float*)g_acc)[i] = 0.f;
    }
}

// ---------------- pre[t][j] = inputs[t]@W_inp + labels[t-1]@(W_lab - W_err) + b_lstm ----------------
__global__ __launch_bounds__(256) void pre_gemm(const float* __restrict__ inputs,
                                                const float* __restrict__ labels,
                                                const float* __restrict__ W_lstm,
                                                const float* __restrict__ b_lstm){
    __shared__ float As[16][132];
    __shared__ float Bs[16][68];
    const int bm = blockIdx.y * 128;
    const int bn = blockIdx.x * 64;
    const int tid = threadIdx.x;
    const int tx = tid & 15, ty = tid >> 4;
    const int atr = tid >> 1, akc = (tid & 1) * 8;
    const int bkr = tid >> 4, bjc = (tid & 15) * 4;

    float acc[8][4];
    #pragma unroll
    for (int u = 0; u < 8; ++u)
        #pragma unroll
        for (int v = 0; v < 4; ++v) acc[u][v] = 0.f;

    for (int k0 = 0; k0 < K_PRE; k0 += 16){
        {
            int t = bm + atr;
            int k = k0 + akc;
            float4 a0, a1;
            if (k0 < D_IN){
                const float* p = &inputs[(size_t)t * D_IN + k];
                a0 = *(const float4*)p; a1 = *(const float4*)(p + 4);
            } else if (t > 0){
                const float* p = &labels[(size_t)(t-1) * O_DIM + (k - D_IN)];
                a0 = *(const float4*)p; a1 = *(const float4*)(p + 4);
            } else {
                a0 = make_float4(0.f,0.f,0.f,0.f); a1 = a0;
            }
            As[akc+0][atr] = a0.x; As[akc+1][atr] = a0.y;
            As[akc+2][atr] = a0.z; As[akc+3][atr] = a0.w;
            As[akc+4][atr] = a1.x; As[akc+5][atr] = a1.y;
            As[akc+6][atr] = a1.z; As[akc+7][atr] = a1.w;
        }
        {
            int krow = k0 + bkr;
            if (krow < D_IN){
                *(float4*)&Bs[bkr][bjc] = *(const float4*)&W_lstm[(size_t)krow * G4 + bn + bjc];
            } else {
                float4 wl = *(const float4*)&W_lstm[(size_t)(krow + 512) * G4 + bn + bjc];
                float4 we = *(const float4*)&W_lstm[(size_t)krow * G4 + bn + bjc];
                float4 d; d.x = wl.x - we.x; d.y = wl.y - we.y; d.z = wl.z - we.z; d.w = wl.w - we.w;
                *(float4*)&Bs[bkr][bjc] = d;
            }
        }
        __syncthreads();
        #pragma unroll
        for (int kk = 0; kk < 16; ++kk){
            float a[8], bb[4];
            *(float4*)&a[0] = *(float4*)&As[kk][ty*8];
            *(float4*)&a[4] = *(float4*)&As[kk][ty*8+4];
            *(float4*)&bb[0] = *(float4*)&Bs[kk][tx*4];
            #pragma unroll
            for (int u = 0; u < 8; ++u)
                #pragma unroll
                for (int v = 0; v < 4; ++v)
                    acc[u][v] = fmaf(a[u], bb[v], acc[u][v]);
        }
        __syncthreads();
    }
    #pragma unroll
    for (int u = 0; u < 8; ++u){
        int t = bm + ty*8 + u;
        int j = bn + tx*4;
        float4 bv = *(const float4*)&b_lstm[j];
        float4 o;
        o.x = acc[u][0] + bv.x; o.y = acc[u][1] + bv.y;
        o.z = acc[u][2] + bv.z; o.w = acc[u][3] + bv.w;
        *(float4*)&g_pre[(size_t)t * G4 + j] = o;
    }
}

// ---------------- persistent stepper ----------------
__global__ __launch_bounds__(TPB, 1) void fw_step(
    const float* __restrict__ W_lstm,
    const float* __restrict__ W_out,
    const float* __restrict__ W_write, const float* __restrict__ W_read,
    const float* __restrict__ b_write, const float* __restrict__ b_read,
    float* __restrict__ dout)
{
    extern __shared__ __align__(16) char dsm[];
    __half2* Wsl    = (__half2*)dsm;                              // [768][32] row-pairs
    __half2* WrwS   = (__half2*)(dsm + WSL_HALF2*4);              // [24][512] p-pairs
    float*   Wslice = (float*)(dsm + (WSL_HALF2 + WRW_HALF2)*4);  // [8][768] proj rows
    __shared__ float xs[XROWS];          // [out(512) | h(1024)]
    __shared__ float mseg[MROW];         // this CTA's full fast-weight memory row (b<48)
    __shared__ float sa[48], sbv[48], sv[48];
    __shared__ float sk1[48], sk2[48], sn[48], se[48];     // prev-step keys
    __shared__ float sk1c[48], sk2c[48], snc[48], sec[48]; // current-step keys
    __shared__ float sdelta[48], snln[48];
    __shared__ float sssp[48];
    __shared__ float pred[16][33];
    __shared__ float sgate[32];
    __shared__ float harr[8];
    __shared__ float c_s[8];
    __shared__ float redf[16];
    __shared__ float red2[16][2];
    __shared__ float sscal[4];           // [0]=upd_beta [1]=upd_inv [2]=beta_raw

    const int tid = threadIdx.x;
    const int b = blockIdx.x;
    const int lane = tid & 31, warp = tid >> 5;
    const bool isMem = (b < NMEM);

    // per-thread memory-row element indices (5 strided segments over 2304)
    int mai[5], mbi[5];
    #pragma unroll
    for (int s = 0; s < 5; ++s){
        int e2 = tid + s*TPB;
        int ai = e2 / 48;
        mai[s] = ai; mbi[s] = e2 - ai*48;
    }

    // ---- one-time init ----
    for (int idx = tid; idx < WSL_HALF2; idx += TPB){
        int p2 = idx >> 5, c = idx & 31;
        int r0 = p2*2, r1 = p2*2 + 1;
        int g0 = (r0 < 512) ? (2048 + r0) : (2560 + r0);  // err rows (take out), then h rows
        int g1 = (r1 < 512) ? (2048 + r1) : (2560 + r1);
        int j = ((c >> 3) << 10) + b*8 + (c & 7);
        float w0 = W_lstm[(size_t)g0 * G4 + j];
        float w1 = W_lstm[(size_t)g1 * G4 + j];
        Wsl[idx] = __floats2half2_rn(w0, w1);
    }
    for (int idx = tid; idx < WRW_HALF2; idx += TPB){
        int p2 = idx >> 9, j = idx & 511;
        WrwS[idx] = __floats2half2_rn(g_Wrw[(p2*2)*O_DIM + j], g_Wrw[(p2*2+1)*O_DIM + j]);
    }
    #pragma unroll
    for (int k = 0; k < 8; ++k){
        int r = b*8 + k;
        for (int j = tid; j < 768; j += TPB){
            float v = 0.f;
            if      (j < 512) v = W_out[(size_t)r*512 + j];
            else if (j < 657) v = W_write[(size_t)r*145 + (j-512)];
            else if (j < 753) v = W_read[(size_t)r*96 + (j-657)];
            Wslice[k*768 + j] = v;
        }
    }
    for (int i = tid; i < MROW; i += TPB) mseg[i] = 0.f;
    if (tid < 8) c_s[tid] = 0.f;
    if (tid < 48){ sdelta[tid]=0.f; sk1[tid]=0.f; sk2[tid]=0.f; snln[tid]=0.f; }
    if (tid == 0){ sscal[0] = 0.f; sscal[1] = 1.f; }
    unsigned tS = 0, tF = 0;
    float pf_h0 = 0.f, pf_h1 = 0.f, pf_uh = 0.f;
    float pf_v = 0.f, pf_k1 = 0.f, pf_k2 = 0.f, pf_n = 0.f, pf_e = 0.f;
    float pf_ssp = 0.f, pf_beta = 0.f;
    __syncthreads();

    for (int t = 0; t < T_STEPS + 1; ++t){
        float* accC = g_acc[t&1];             // current-step accumulator

        // ======== phaseOut: finish step t-1 (scalars, out) — uses window prefetches ========
        if (t > 0){
            if (tid < 48){
                sa[tid]  = __ldcg(&g_ap[tid]);
                sbv[tid] = __ldcg(&g_bp[tid]);
                sv[tid]  = tanhf(pf_v);
                sk1[tid] = tanhf(pf_k1);
                sk2[tid] = tanhf(pf_k2);
                sn[tid]  = tanhf(pf_n);
                se[tid]  = tanhf(pf_e);
            }
            if (tid >= 64 && tid < 112) sssp[tid-64] = pf_ssp;
            if (tid == 63) sscal[2] = pf_beta;
            __syncthreads();
            if (tid < 32){
                const int l = tid; const bool h1 = (l < 16); const int i1 = l + 32;
                float SS  = wsum(sssp[l] + (h1 ? sssp[i1] : 0.f));
                float k1n = wsum(sk1[l]*sn[l]  + (h1 ? sk1[i1]*sn[i1] : 0.f));
                float k2e = wsum(sk2[l]*se[l]  + (h1 ? sk2[i1]*se[i1] : 0.f));
                float k1q = wsum(sk1[l]*sk1[l] + (h1 ? sk1[i1]*sk1[i1] : 0.f));
                float k2q = wsum(sk2[l]*sk2[l] + (h1 ? sk2[i1]*sk2[i1] : 0.f));
                float invc = 1.f / fmaxf(1.f, sqrtf(SS));
                float beta = sigf(sscal[2]);
                float d0 = sv[l] - invc*sa[l];
                float d1 = h1 ? (sv[i1] - invc*sa[i1]) : 0.f;
                float da = wsum(d0*sa[l] + (h1 ? d1*sa[i1] : 0.f));
                float dd = wsum(d0*d0 + d1*d1);
                float skr = k1n * k2e;
                float SSP = invc*invc*SS + 2.f*invc*beta*da + beta*beta*dd*k1q*k2q;
                float invn = 1.f / fmaxf(1.f, sqrtf(SSP));
                float nv0 = invn * (invc*sbv[l]  + beta*d0*skr);
                float nv1 = h1 ? invn * (invc*sbv[i1] + beta*d1*skr) : 0.f;
                float mean = wsum(nv0 + nv1) * (1.f/48.f);
                float c0 = nv0 - mean, c1 = nv1 - mean;
                float var = wsum(c0*c0 + (h1 ? c1*c1 : 0.f)) * (1.f/48.f);
                float rs = 1.f / sqrtf(var + LN_EPS);
                snln[l] = c0 * rs;
                if (h1) snln[i1] = c1 * rs;
                sdelta[l] = d0;
                if (h1) sdelta[i1] = d1;
                if (l == 0){ sscal[0] = beta; sscal[1] = invc; }
            }
            __syncthreads();
            // out_{t-1}: one column per thread; Wrw from SMEM (fp16 pairs)
            {
                const int j = tid;
                float o = pf_uh + g_bcomb[j];
                #pragma unroll
                for (int p2 = 0; p2 < 24; ++p2){
                    float2 w = __half22float2(WrwS[p2*512 + j]);
                    o = fmaf(snln[p2*2], w.x, fmaf(snln[p2*2+1], w.y, o));
                }
                o = tanhf(o * 0.1f) * 10.f;
                if (b == 0) dout[(size_t)(t-1)*O_DIM + j] = o;
                xs[j] = o;
            }
            xs[512  + tid] = pf_h0;
            xs[1024 + tid] = pf_h1;
        } else {
            for (int i = tid; i < XROWS; i += TPB) xs[i] = 0.f;
        }
        if (t == T_STEPS) break;
        __syncthreads();

        // ======== phase 1: gates + cell + mseg update + partial projections ========
        {
            float gp = 0.f;
            if (tid < 32){
                int j = ((tid >> 3) << 10) + b*8 + (tid & 7);
                gp = __ldg(&g_pre[(size_t)t * G4 + j]);
            }
            const int c = lane, rc = warp;
            const int r0 = rc * 96;          // xs row base
            const int pr0 = rc * 48;         // pair base
            float acc = 0.f;
            #pragma unroll
            for (int pp = 0; pp < 48; pp += 2){
                float4 xv = *(float4*)&xs[r0 + pp*2];
                float2 w0 = __half22float2(Wsl[(pr0+pp  )*32 + c]);
                float2 w1 = __half22float2(Wsl[(pr0+pp+1)*32 + c]);
                acc = fmaf(xv.x, w0.x, acc);
                acc = fmaf(xv.y, w0.y, acc);
                acc = fmaf(xv.z, w1.x, acc);
                acc = fmaf(xv.w, w1.y, acc);
            }
            pred[rc][c] = acc;

            // fast-weight physical row update (prev-step params) + sum-of-squares
            if (isMem){
                const float coef = sscal[0] * sdelta[b];
                const float uinv = sscal[1];
                float fss = 0.f;
                #pragma unroll
                for (int s = 0; s < 5; ++s){
                    int e2 = tid + s*TPB;
                    if (e2 < MROW){
                        float m = fmaf(coef, sk1[mai[s]]*sk2[mbi[s]], uinv * mseg[e2]);
                        mseg[e2] = m;
                        fss = fmaf(m, m, fss);
                    }
                }
                fss = wsum(fss);
                if (lane == 0) redf[warp] = fss;
            }
            __syncthreads();
            if (tid < 32){
                float g = 0.f;
                #pragma unroll
                for (int r2 = 0; r2 < 16; ++r2) g += pred[r2][tid];
                sgate[tid] = g + gp;
            }
            if (tid == 32 && isMem){
                float s = 0.f;
                #pragma unroll
                for (int w = 0; w < 16; ++w) s += redf[w];
                __stcg(&g_ssp[t&1][b], s);
            }
            __syncthreads();
            if (tid < 8){
                float iv = sgate[tid], gv = sgate[8+tid], fv = sgate[16+tid], ov = sgate[24+tid];
                float cn = sigf(fv + 1.f) * c_s[tid] + sigf(iv) * tanhf(gv);
                c_s[tid] = cn;
                float hv = sigf(ov) * tanhf(cn);
                harr[tid] = hv;
                __stcg(&g_h[t&1][b*8 + tid], hv);
            }
            __syncthreads();
            // partial projections: this CTA's 8 h-rows into all 753 columns (dense atomics)
            {
                float vA = 0.f;
                #pragma unroll
                for (int k = 0; k < 8; ++k)
                    vA = fmaf(harr[k], Wslice[k*768 + tid], vA);
                atomicAdd(&accC[tid], vA);
                if (tid < 241){
                    float vB = 0.f;
                    #pragma unroll
                    for (int k = 0; k < 8; ++k)
                        vB = fmaf(harr[k], Wslice[k*768 + 512 + tid], vB);
                    atomicAdd(&accC[512 + tid], vB);
                }
            }
        }
        // ---- S12: full barrier (release arrival) ----
        __syncthreads();
        if (tid == 0) red_release(&g_cS12[0]);
        tS += NCTA;
        if (tid == 0){ while (ld_acq(&g_cS12[0]) < tS) {} }
        __syncthreads();

        // ======== phase 3: memory dots (mem CTAs) + next-parity zeroing (all) ========
        if (isMem){
            if (tid < 48){
                sk1c[tid] = tanhf(__ldcg(&accC[512+tid]) + __ldg(&b_write[tid]));
                sk2c[tid] = tanhf(__ldcg(&accC[560+tid]) + __ldg(&b_write[48+tid]));
                snc[tid]  = tanhf(__ldcg(&accC[657+tid]) + __ldg(&b_read[tid]));
                sec[tid]  = tanhf(__ldcg(&accC[705+tid]) + __ldg(&b_read[48+tid]));
            }
            __syncthreads();
            float fa = 0.f, fb = 0.f;
            #pragma unroll
            for (int s = 0; s < 5; ++s){
                int e2 = tid + s*TPB;
                if (e2 < MROW){
                    float m = mseg[e2];
                    fa = fmaf(m, sk1c[mai[s]]*sk2c[mbi[s]], fa);
                    fb = fmaf(m, snc[mai[s]]*sec[mbi[s]], fb);
                }
            }
            #pragma unroll
            for (int o = 16; o > 0; o >>= 1){
                fa += __shfl_xor_sync(0xffffffffu, fa, o);
                fb += __shfl_xor_sync(0xffffffffu, fb, o);
            }
            if (lane == 0){ red2[warp][0] = fa; red2[warp][1] = fb; }
            __syncthreads();
            if (tid == 0){
                float A = 0.f, B = 0.f;
                #pragma unroll
                for (int w = 0; w < 16; ++w){ A += red2[w][0]; B += red2[w][1]; }
                __stcg(&g_ap[b], A);
                __stcg(&g_bp[b], B);
            }
        }
        // zero own columns of the NEXT-parity accumulator (safe: after S12(t), all readers done)
        if (tid < 6){
            int co = b*6 + tid;
            if (co < 753) __stcg(&g_acc[(t+1)&1][co], 0.f);
        }
        // ---- window prefetches for phaseOut(t+1): accC/ssp are final after S12(t) ----
        pf_h0 = __ldcg(&g_h[t&1][tid]);
        pf_h1 = __ldcg(&g_h[t&1][512 + tid]);
        pf_uh = __ldcg(&accC[tid]);
        if (tid < 48){
            pf_v  = __ldcg(&accC[608+tid]) + __ldg(&b_write[96+tid]);
            pf_k1 = __ldcg(&accC[512+tid]) + __ldg(&b_write[tid]);
            pf_k2 = __ldcg(&accC[560+tid]) + __ldg(&b_write[48+tid]);
            pf_n  = __ldcg(&accC[657+tid]) + __ldg(&b_read[tid]);
            pf_e  = __ldcg(&accC[705+tid]) + __ldg(&b_read[48+tid]);
        }
        if (tid >= 64 && tid < 112) pf_ssp = __ldcg(&g_ssp[t&1][tid-64]);
        if (tid == 63) pf_beta = __ldcg(&accC[656]) + __ldg(&b_write[144]);
        // ---- F: full barrier (release arrival) ----
        __syncthreads();
        if (tid == 0) red_release(&g_cF[0]);
        tF += NCTA;
        if (tid == 0){ while (ld_acq(&g_cF[0]) < tF) {} }
        __syncthreads();
    }
}

// ---------------- launch ----------------
extern "C" void kernel_launch(void* const* d_in, const int* in_sizes, int n_in,
                              void* d_out, int out_size) {
    const float* inputs  = (const float*)d_in[0];
    const float* labels  = (const float*)d_in[1];
    const float* W_lstm  = (const float*)d_in[2];
    const float* b_lstm  = (const float*)d_in[3];
    const float* W_write = (const float*)d_in[4];
    const float* b_write = (const float*)d_in[5];
    const float* W_read  = (const float*)d_in[6];
    const float* b_read  = (const float*)d_in[7];
    const float* W_rproj = (const float*)d_in[8];
    const float* b_rproj = (const float*)d_in[9];
    const float* W_out   = (const float*)d_in[10];
    const float* b_out   = (const float*)d_in[11];
    float* out = (float*)d_out;

    cudaFuncSetAttribute(fw_step, cudaFuncAttributeMaxDynamicSharedMemorySize, DYN_SMEM);

    fw_dummy0<<<1, 32>>>();
    fw_dummy1<<<1, 32>>>();
    fw_dummy2<<<1, 32>>>();
    fw_dummy3<<<1, 32>>>();
    fw_dummy4<<<1, 32>>>();
    fw_setup<<<50, 512>>>(W_rproj, b_rproj, W_out, b_out);
    pre_gemm<<<dim3(64, 8), 256>>>(inputs, labels, W_lstm, b_lstm);
    fw_step<<<NCTA, TPB, DYN_SMEM>>>(W_lstm, W_out, W_write, W_read, b_write, b_read, out);
}